// round 2
// baseline (speedup 1.0000x reference)
#include <cuda_runtime.h>
#include <cstdint>

// ---------------- problem constants ----------------
#define BB 2
#define N0 8192
#define N1 4096
#define N2 2048
#define KNBR 16

// ---------------- one big scratch buffer (no allocs allowed) ----------------
__device__ float g_buf[16 * 1024 * 1024]; // 64 MB

// offsets in floats (all 256-aligned)
#define ALIGN256(x) (((x) + 255) & ~255)
static const size_t OFF_IDX0  = 0;                                   // 2*8192*16 ints
static const size_t OFF_IDX1  = ALIGN256(OFF_IDX0  + 2*8192*16);     // 2*4096*16
static const size_t OFF_IDX2  = ALIGN256(OFF_IDX1  + 2*4096*16);     // 2*2048*16
static const size_t OFF_FPS1  = ALIGN256(OFF_IDX2  + 2*2048*16);     // 2*4096
static const size_t OFF_FPS2  = ALIGN256(OFF_FPS1  + 2*4096);        // 2*2048
static const size_t OFF_POS1  = ALIGN256(OFF_FPS2  + 2*2048);        // 2*4096*3
static const size_t OFF_POS2  = ALIGN256(OFF_POS1  + 2*4096*3);      // 2*2048*3
static const size_t OFF_FEAT0 = ALIGN256(OFF_POS2  + 2*2048*3);      // 2*8192*64
static const size_t OFF_FG1   = ALIGN256(OFF_FEAT0 + 2*8192*64);     // 2*4096*64
static const size_t OFF_FEAT1 = ALIGN256(OFF_FG1   + 2*4096*64);     // 2*4096*128
static const size_t OFF_FG2   = ALIGN256(OFF_FEAT1 + 2*4096*128);    // 2*2048*128
static const size_t OFF_FEAT2 = ALIGN256(OFF_FG2   + 2*2048*128);    // 2*2048*256
static const size_t OFF_NNI1  = ALIGN256(OFF_FEAT2 + 2*2048*256);    // 2*4096*3 ints
static const size_t OFF_NNW1  = ALIGN256(OFF_NNI1  + 2*4096*3);      // 2*4096*3
static const size_t OFF_NNI0  = ALIGN256(OFF_NNW1  + 2*4096*3);      // 2*8192*3 ints
static const size_t OFF_NNW0  = ALIGN256(OFF_NNI0  + 2*8192*3);      // 2*8192*3
static const size_t OFF_FU1P  = ALIGN256(OFF_NNW0  + 2*8192*3);      // 2*4096*128
static const size_t OFF_FU1   = ALIGN256(OFF_FU1P  + 2*4096*128);    // 2*4096*128
static const size_t OFF_FU0   = ALIGN256(OFF_FU1   + 2*4096*128);    // 2*8192*64
static const size_t OFF_FOUT  = ALIGN256(OFF_FU0   + 2*8192*64);     // 2*8192*64
static const size_t OFF_ACAT  = ALIGN256(OFF_FOUT  + 2*8192*64);     // 16384*384
static const size_t OFF_WCAT  = ALIGN256(OFF_ACAT  + (size_t)16384*384); // 384*256

// ---------------- KNN: brute force, top-16 register insertion ----------------
__global__ void knn_kernel(const float* __restrict__ pos, int N, int* __restrict__ outIdx)
{
    const int TILE = 512;
    __shared__ float sx[512], sy[512], sz[512], sn[512];
    int b = blockIdx.y;
    const float* P = pos + (size_t)b * N * 3;
    int i = blockIdx.x * blockDim.x + threadIdx.x;

    float qx = P[i*3+0], qy = P[i*3+1], qz = P[i*3+2];
    float qn = __fadd_rn(__fadd_rn(__fmul_rn(qx,qx), __fmul_rn(qy,qy)), __fmul_rn(qz,qz));

    float bd[KNBR]; int bi[KNBR];
#pragma unroll
    for (int t = 0; t < KNBR; ++t) { bd[t] = 3.0e38f; bi[t] = -1; }

    for (int j0 = 0; j0 < N; j0 += TILE) {
        for (int t = threadIdx.x; t < TILE; t += blockDim.x) {
            float x = P[(j0+t)*3+0], y = P[(j0+t)*3+1], z = P[(j0+t)*3+2];
            sx[t] = x; sy[t] = y; sz[t] = z;
            sn[t] = __fadd_rn(__fadd_rn(__fmul_rn(x,x), __fmul_rn(y,y)), __fmul_rn(z,z));
        }
        __syncthreads();
        for (int t = 0; t < TILE; ++t) {
            float dot = __fadd_rn(__fadd_rn(__fmul_rn(qx,sx[t]), __fmul_rn(qy,sy[t])), __fmul_rn(qz,sz[t]));
            float d = __fsub_rn(__fadd_rn(qn, sn[t]), __fmul_rn(2.0f, dot));
            if (d < bd[KNBR-1]) {
                bd[KNBR-1] = d; bi[KNBR-1] = j0 + t;
#pragma unroll
                for (int s = KNBR-1; s > 0; --s) {
                    if (bd[s] < bd[s-1]) {
                        float tv = bd[s]; bd[s] = bd[s-1]; bd[s-1] = tv;
                        int ti = bi[s]; bi[s] = bi[s-1]; bi[s-1] = ti;
                    }
                }
            }
        }
        __syncthreads();
    }
    int* O = outIdx + ((size_t)b * N + i) * KNBR;
#pragma unroll
    for (int t = 0; t < KNBR; ++t) O[t] = bi[t];
}

// ---------------- FPS: one block per batch, sequential ----------------
template<int PPT>
__global__ void fps_kernel(const float* __restrict__ pos, int N, int npoint,
                           int* __restrict__ outIdx, float* __restrict__ outPos)
{
    const int NT = 512;
    int b = blockIdx.x;
    const float* P = pos + (size_t)b * N * 3;
    int tid = threadIdx.x;

    float px[PPT], py[PPT], pz[PPT], dd[PPT];
#pragma unroll
    for (int p = 0; p < PPT; ++p) {
        int gi = tid + p * NT;
        px[p] = P[gi*3+0]; py[p] = P[gi*3+1]; pz[p] = P[gi*3+2];
        dd[p] = 1e10f;
    }

    __shared__ float sv[16];
    __shared__ int   si[16];
    __shared__ float scx, scy, scz;
    __shared__ int   sfar;

    float cx = P[0], cy = P[1], cz = P[2];
    int far = 0;

    for (int it = 0; it < npoint; ++it) {
        if (tid == 0) {
            outIdx[(size_t)b * npoint + it] = far;
            outPos[((size_t)b * npoint + it) * 3 + 0] = cx;
            outPos[((size_t)b * npoint + it) * 3 + 1] = cy;
            outPos[((size_t)b * npoint + it) * 3 + 2] = cz;
        }
        float bv = -1.0f; int bidx = 0x7fffffff;
#pragma unroll
        for (int p = 0; p < PPT; ++p) {
            float dx = __fsub_rn(px[p], cx);
            float dy = __fsub_rn(py[p], cy);
            float dz = __fsub_rn(pz[p], cz);
            float d = __fadd_rn(__fadd_rn(__fmul_rn(dx,dx), __fmul_rn(dy,dy)), __fmul_rn(dz,dz));
            float nd = fminf(dd[p], d);
            dd[p] = nd;
            if (nd > bv) { bv = nd; bidx = tid + p * NT; }
            else if (nd == bv && (tid + p * NT) < bidx) { bidx = tid + p * NT; }
        }
#pragma unroll
        for (int o = 16; o > 0; o >>= 1) {
            float ov = __shfl_down_sync(0xffffffffu, bv, o);
            int   oi = __shfl_down_sync(0xffffffffu, bidx, o);
            if (ov > bv || (ov == bv && oi < bidx)) { bv = ov; bidx = oi; }
        }
        if ((tid & 31) == 0) { sv[tid >> 5] = bv; si[tid >> 5] = bidx; }
        __syncthreads();
        if (tid < 32) {
            float bv2 = (tid < 16) ? sv[tid] : -2.0f;
            int   bi2 = (tid < 16) ? si[tid] : 0x7fffffff;
#pragma unroll
            for (int o = 8; o > 0; o >>= 1) {
                float ov = __shfl_down_sync(0xffffffffu, bv2, o);
                int   oi = __shfl_down_sync(0xffffffffu, bi2, o);
                if (ov > bv2 || (ov == bv2 && oi < bi2)) { bv2 = ov; bi2 = oi; }
            }
            if (tid == 0) {
                sfar = bi2;
                scx = P[bi2*3+0]; scy = P[bi2*3+1]; scz = P[bi2*3+2];
            }
        }
        __syncthreads();
        far = sfar; cx = scx; cy = scy; cz = scz;
    }
}

// ---------------- edge-conv phase A: Acat row = [x_i | mean nx | mean rel | mean d2] ----------------
__global__ void hbar_kernel(const float* __restrict__ xf, const float* __restrict__ pos,
                            const int* __restrict__ knn, int N, int C,
                            float* __restrict__ Acat, int ldA)
{
    int gw = (blockIdx.x * blockDim.x + threadIdx.x) >> 5;
    int lane = threadIdx.x & 31;
    if (gw >= BB * N) return;
    int b = gw / N, i = gw % N;
    const float* Pb = pos + (size_t)b * N * 3;
    const float* Xb = xf + (size_t)b * N * C;
    const int* nbr = knn + (size_t)gw * KNBR;

    int j = (lane < KNBR) ? nbr[lane] : 0;
    float rx = 0.f, ry = 0.f, rz = 0.f, d2 = 0.f;
    if (lane < KNBR) {
        float qx = Pb[i*3+0], qy = Pb[i*3+1], qz = Pb[i*3+2];
        rx = qx - Pb[j*3+0]; ry = qy - Pb[j*3+1]; rz = qz - Pb[j*3+2];
        d2 = (rx*rx + ry*ry) + rz*rz;
    }

    // broadcast neighbor indices to ALL lanes while warp is converged
    int jlist[KNBR];
#pragma unroll
    for (int kk = 0; kk < KNBR; ++kk)
        jlist[kk] = __shfl_sync(0xffffffffu, j, kk);

#pragma unroll
    for (int o = 16; o > 0; o >>= 1) {
        rx += __shfl_down_sync(0xffffffffu, rx, o);
        ry += __shfl_down_sync(0xffffffffu, ry, o);
        rz += __shfl_down_sync(0xffffffffu, rz, o);
        d2 += __shfl_down_sync(0xffffffffu, d2, o);
    }
    float* Arow = Acat + (size_t)gw * ldA;
    if (lane == 0) {
        const float inv = 1.0f / 16.0f;
        Arow[2*C + 0] = rx * inv;
        Arow[2*C + 1] = ry * inv;
        Arow[2*C + 2] = rz * inv;
        Arow[2*C + 3] = d2 * inv;
    }
    for (int c = lane; c < C; c += 32) {
        float acc = 0.f;
#pragma unroll
        for (int kk = 0; kk < KNBR; ++kk)
            acc += Xb[(size_t)jlist[kk] * C + c];
        Arow[c]     = Xb[(size_t)i * C + c];
        Arow[C + c] = acc * (1.0f / 16.0f);
    }
}

// ---------------- generic tiled SGEMM: C = act(A@W + bias) ----------------
__global__ void sgemm_kernel(const float* __restrict__ A, int ldA,
                             const float* __restrict__ W,
                             const float* __restrict__ bias,
                             float* __restrict__ Cout,
                             int M, int N, int Kd, int act)
{
    __shared__ float As[16][64];
    __shared__ float Ws[16][64];
    int tid = threadIdx.x;
    int rowBase = blockIdx.y * 64, colBase = blockIdx.x * 64;
    int tx = tid & 15, ty = tid >> 4;
    float acc[4][4] = {};
    int lrow = tid >> 2, lk4 = (tid & 3) * 4;
    int wrow = tid >> 4, wcol4 = (tid & 15) * 4;

    for (int k0 = 0; k0 < Kd; k0 += 16) {
#pragma unroll
        for (int q = 0; q < 4; ++q) {
            int k = k0 + lk4 + q;
            As[lk4 + q][lrow] = (k < Kd) ? A[(size_t)(rowBase + lrow) * ldA + k] : 0.0f;
        }
        {
            int k = k0 + wrow;
#pragma unroll
            for (int q = 0; q < 4; ++q)
                Ws[wrow][wcol4 + q] = (k < Kd) ? W[(size_t)k * N + colBase + wcol4 + q] : 0.0f;
        }
        __syncthreads();
#pragma unroll
        for (int kk = 0; kk < 16; ++kk) {
            float a[4], wv[4];
#pragma unroll
            for (int q = 0; q < 4; ++q) a[q] = As[kk][ty * 4 + q];
#pragma unroll
            for (int q = 0; q < 4; ++q) wv[q] = Ws[kk][tx * 4 + q];
#pragma unroll
            for (int q = 0; q < 4; ++q)
#pragma unroll
                for (int r = 0; r < 4; ++r)
                    acc[q][r] = fmaf(a[q], wv[r], acc[q][r]);
        }
        __syncthreads();
    }
#pragma unroll
    for (int q = 0; q < 4; ++q) {
        int m = rowBase + ty * 4 + q;
#pragma unroll
        for (int r = 0; r < 4; ++r) {
            int n = colBase + tx * 4 + r;
            float v = acc[q][r];
            if (bias) v += bias[n];
            if (act) v = (v >= 0.f) ? v : 0.2f * v;
            Cout[(size_t)m * N + n] = v;
        }
    }
}

// ---------------- gather: out[b,m,:] = src[b, idx[b,m], :] ----------------
__global__ void gather_kernel(const float* __restrict__ src, int C, int Nsrc,
                              const int* __restrict__ idx, int Mper, float* __restrict__ dst)
{
    int t = blockIdx.x * blockDim.x + threadIdx.x;
    int total = BB * Mper * C;
    if (t >= total) return;
    int c = t % C; int row = t / C; int b = row / Mper;
    dst[t] = src[((size_t)b * Nsrc + idx[row]) * C + c];
}

// ---------------- three_nn: top-3 + weights ----------------
__global__ void three_nn_kernel(const float* __restrict__ unk, int Nu,
                                const float* __restrict__ knw, int Nk,
                                int* __restrict__ outIdx, float* __restrict__ outW)
{
    const int TILE = 512;
    __shared__ float sx[512], sy[512], sz[512], sn[512];
    int b = blockIdx.y;
    const float* U = unk + (size_t)b * Nu * 3;
    const float* Kp = knw + (size_t)b * Nk * 3;
    int i = blockIdx.x * blockDim.x + threadIdx.x;

    float qx = U[i*3+0], qy = U[i*3+1], qz = U[i*3+2];
    float qn = __fadd_rn(__fadd_rn(__fmul_rn(qx,qx), __fmul_rn(qy,qy)), __fmul_rn(qz,qz));
    float b0 = 3e38f, b1 = 3e38f, b2 = 3e38f;
    int   i0 = -1, i1 = -1, i2 = -1;

    for (int j0 = 0; j0 < Nk; j0 += TILE) {
        for (int t = threadIdx.x; t < TILE; t += blockDim.x) {
            float x = Kp[(j0+t)*3+0], y = Kp[(j0+t)*3+1], z = Kp[(j0+t)*3+2];
            sx[t] = x; sy[t] = y; sz[t] = z;
            sn[t] = __fadd_rn(__fadd_rn(__fmul_rn(x,x), __fmul_rn(y,y)), __fmul_rn(z,z));
        }
        __syncthreads();
        for (int t = 0; t < TILE; ++t) {
            float dot = __fadd_rn(__fadd_rn(__fmul_rn(qx,sx[t]), __fmul_rn(qy,sy[t])), __fmul_rn(qz,sz[t]));
            float d = __fsub_rn(__fadd_rn(qn, sn[t]), __fmul_rn(2.0f, dot));
            int j = j0 + t;
            if (d < b2) {
                if (d < b0)      { b2 = b1; i2 = i1; b1 = b0; i1 = i0; b0 = d; i0 = j; }
                else if (d < b1) { b2 = b1; i2 = i1; b1 = d;  i1 = j; }
                else             { b2 = d;  i2 = j; }
            }
        }
        __syncthreads();
    }
    b0 = fmaxf(b0, 0.f); b1 = fmaxf(b1, 0.f); b2 = fmaxf(b2, 0.f);
    float r0 = 1.0f / (b0 + 1e-8f), r1 = 1.0f / (b1 + 1e-8f), r2 = 1.0f / (b2 + 1e-8f);
    float s = (r0 + r1) + r2;
    size_t o = ((size_t)b * Nu + i) * 3;
    outIdx[o+0] = i0; outIdx[o+1] = i1; outIdx[o+2] = i2;
    outW[o+0] = r0 / s; outW[o+1] = r1 / s; outW[o+2] = r2 / s;
}

// ---------------- three_interp into Acat columns ----------------
__global__ void interp_kernel(const float* __restrict__ feat, int C, int Nsrc,
                              const int* __restrict__ idx3, const float* __restrict__ w3,
                              int Mper, float* __restrict__ dst, int ldD, int colOff)
{
    int t = blockIdx.x * blockDim.x + threadIdx.x;
    int total = BB * Mper * C;
    if (t >= total) return;
    int c = t % C; int row = t / C; int b = row / Mper;
    const int* I = idx3 + (size_t)row * 3;
    const float* Wt = w3 + (size_t)row * 3;
    const float* F = feat + (size_t)b * Nsrc * C;
    float v = Wt[0] * F[(size_t)I[0] * C + c]
            + Wt[1] * F[(size_t)I[1] * C + c]
            + Wt[2] * F[(size_t)I[2] * C + c];
    dst[(size_t)row * ldD + colOff + c] = v;
}

// ---------------- strided column copy into Acat ----------------
__global__ void copy_cols_kernel(const float* __restrict__ src, int cols, int Mtot,
                                 float* __restrict__ dst, int ldD, int colOff)
{
    int t = blockIdx.x * blockDim.x + threadIdx.x;
    int total = Mtot * cols;
    if (t >= total) return;
    int c = t % cols; int row = t / cols;
    dst[(size_t)row * ldD + colOff + c] = src[t];
}

// ---------------- host orchestration ----------------
static inline void gemm(const float* A, int ldA, const float* W, const float* bias,
                        float* C, int M, int N, int Kd, int act)
{
    dim3 grid(N / 64, M / 64);
    sgemm_kernel<<<grid, 256>>>(A, ldA, W, bias, C, M, N, Kd, act);
}

extern "C" void kernel_launch(void* const* d_in, const int* in_sizes, int n_in,
                              void* d_out, int out_size)
{
    const float* x          = (const float*)d_in[0];
    const float* pos        = (const float*)d_in[1];
    const float* w_self0    = (const float*)d_in[2];
    const float* w_edge0    = (const float*)d_in[3];
    const float* w_self1    = (const float*)d_in[4];
    const float* w_edge1    = (const float*)d_in[5];
    const float* w_self2    = (const float*)d_in[6];
    const float* w_edge2    = (const float*)d_in[7];
    const float* w_up1      = (const float*)d_in[8];
    const float* b_up1      = (const float*)d_in[9];
    const float* w_upc1_self= (const float*)d_in[10];
    const float* w_upc1_edge= (const float*)d_in[11];
    const float* w_up0      = (const float*)d_in[12];
    const float* b_up0      = (const float*)d_in[13];
    const float* w_upc0_self= (const float*)d_in[14];
    const float* w_upc0_edge= (const float*)d_in[15];
    const float* w_out      = (const float*)d_in[16];
    const float* b_out      = (const float*)d_in[17];

    float* base = nullptr;
    cudaGetSymbolAddress((void**)&base, g_buf);

    int*   idx0  = (int*)(base + OFF_IDX0);
    int*   idx1  = (int*)(base + OFF_IDX1);
    int*   idx2  = (int*)(base + OFF_IDX2);
    int*   fps1  = (int*)(base + OFF_FPS1);
    int*   fps2  = (int*)(base + OFF_FPS2);
    float* pos1  = base + OFF_POS1;
    float* pos2  = base + OFF_POS2;
    float* feat0 = base + OFF_FEAT0;
    float* fg1   = base + OFF_FG1;
    float* feat1 = base + OFF_FEAT1;
    float* fg2   = base + OFF_FG2;
    float* feat2 = base + OFF_FEAT2;
    int*   nni1  = (int*)(base + OFF_NNI1);
    float* nnw1  = base + OFF_NNW1;
    int*   nni0  = (int*)(base + OFF_NNI0);
    float* nnw0  = base + OFF_NNW0;
    float* fu1p  = base + OFF_FU1P;
    float* fu1   = base + OFF_FU1;
    float* fu0   = base + OFF_FU0;
    float* fout  = base + OFF_FOUT;
    float* Acat  = base + OFF_ACAT;
    float* Wcat  = base + OFF_WCAT;

    // ---- level 0 edge conv: C=4, Kcat=12, N=64 ----
    knn_kernel<<<dim3(N0/256, BB), 256>>>(pos, N0, idx0);
    hbar_kernel<<<(BB*N0)/4, 128>>>(x, pos, idx0, N0, 4, Acat, 12);
    cudaMemcpyAsync(Wcat,         w_self0, (size_t)4*64*4, cudaMemcpyDeviceToDevice, 0);
    cudaMemcpyAsync(Wcat + 4*64,  w_edge0, (size_t)8*64*4, cudaMemcpyDeviceToDevice, 0);
    gemm(Acat, 12, Wcat, nullptr, feat0, BB*N0, 64, 12, 1);

    // ---- FPS 8192 -> 4096, gather ----
    fps_kernel<16><<<BB, 512>>>(pos, N0, N1, fps1, pos1);
    gather_kernel<<<(BB*N1*64 + 255)/256, 256>>>(feat0, 64, N0, fps1, N1, fg1);

    // ---- level 1 edge conv: C=64, Kcat=132, N=128 ----
    knn_kernel<<<dim3(N1/256, BB), 256>>>(pos1, N1, idx1);
    hbar_kernel<<<(BB*N1)/4, 128>>>(fg1, pos1, idx1, N1, 64, Acat, 132);
    cudaMemcpyAsync(Wcat,          w_self1, (size_t)64*128*4, cudaMemcpyDeviceToDevice, 0);
    cudaMemcpyAsync(Wcat + 64*128, w_edge1, (size_t)68*128*4, cudaMemcpyDeviceToDevice, 0);
    gemm(Acat, 132, Wcat, nullptr, feat1, BB*N1, 128, 132, 1);

    // ---- FPS 4096 -> 2048, gather ----
    fps_kernel<8><<<BB, 512>>>(pos1, N1, N2, fps2, pos2);
    gather_kernel<<<(BB*N2*128 + 255)/256, 256>>>(feat1, 128, N1, fps2, N2, fg2);

    // ---- level 2 edge conv: C=128, Kcat=260, N=256 ----
    knn_kernel<<<dim3(N2/256, BB), 256>>>(pos2, N2, idx2);
    hbar_kernel<<<(BB*N2)/4, 128>>>(fg2, pos2, idx2, N2, 128, Acat, 260);
    cudaMemcpyAsync(Wcat,           w_self2, (size_t)128*256*4, cudaMemcpyDeviceToDevice, 0);
    cudaMemcpyAsync(Wcat + 128*256, w_edge2, (size_t)132*256*4, cudaMemcpyDeviceToDevice, 0);
    gemm(Acat, 260, Wcat, nullptr, feat2, BB*N2, 256, 260, 1);

    // ---- up 1: three_nn(pos1, pos2), interp feat2, cat feat1, linear ----
    three_nn_kernel<<<dim3(N1/256, BB), 256>>>(pos1, N1, pos2, N2, nni1, nnw1);
    interp_kernel<<<(BB*N1*256 + 255)/256, 256>>>(feat2, 256, N2, nni1, nnw1, N1, Acat, 384, 0);
    copy_cols_kernel<<<(BB*N1*128 + 255)/256, 256>>>(feat1, 128, BB*N1, Acat, 384, 256);
    gemm(Acat, 384, w_up1, b_up1, fu1p, BB*N1, 128, 384, 1);

    // ---- up 1 edge conv (reuse idx1): C=128, Kcat=260, N=128 ----
    hbar_kernel<<<(BB*N1)/4, 128>>>(fu1p, pos1, idx1, N1, 128, Acat, 260);
    cudaMemcpyAsync(Wcat,           w_upc1_self, (size_t)128*128*4, cudaMemcpyDeviceToDevice, 0);
    cudaMemcpyAsync(Wcat + 128*128, w_upc1_edge, (size_t)132*128*4, cudaMemcpyDeviceToDevice, 0);
    gemm(Acat, 260, Wcat, nullptr, fu1, BB*N1, 128, 260, 1);

    // ---- up 0: three_nn(pos0, pos1), interp fu1, cat feat0, linear ----
    three_nn_kernel<<<dim3(N0/256, BB), 256>>>(pos, N0, pos1, N1, nni0, nnw0);
    interp_kernel<<<(BB*N0*128 + 255)/256, 256>>>(fu1, 128, N1, nni0, nnw0, N0, Acat, 192, 0);
    copy_cols_kernel<<<(BB*N0*64 + 255)/256, 256>>>(feat0, 64, BB*N0, Acat, 192, 128);
    gemm(Acat, 192, w_up0, b_up0, fu0, BB*N0, 64, 192, 1);

    // ---- up 0 edge conv (reuse idx0): C=64, Kcat=132, N=64 ----
    hbar_kernel<<<(BB*N0)/4, 128>>>(fu0, pos, idx0, N0, 64, Acat, 132);
    cudaMemcpyAsync(Wcat,         w_upc0_self, (size_t)64*64*4, cudaMemcpyDeviceToDevice, 0);
    cudaMemcpyAsync(Wcat + 64*64, w_upc0_edge, (size_t)68*64*4, cudaMemcpyDeviceToDevice, 0);
    gemm(Acat, 132, Wcat, nullptr, fout, BB*N0, 64, 132, 1);

    // ---- output projection: no activation ----
    gemm(fout, 64, w_out, b_out, (float*)d_out, BB*N0, 128, 64, 0);
}